// round 2
// baseline (speedup 1.0000x reference)
#include <cuda_runtime.h>
#include <math.h>

#define TT 2048
#define HH 1024
#define II 1024
#define NE 16
#define KTOP 4
#define EPSF 1e-5f
#define ALPHAF 1.702f
#define LIMITF 7.0f

#define BM 64
#define BN 64
#define BK 16

// ---------------- scratch (static device globals; no allocation) -------------
__device__ __align__(16) float g_t[TT * HH];            // 8 MB   rmsnorm output
__device__ __align__(16) float g_s[TT * KTOP * II];     // 32 MB  swiglu activations per slot
__device__ __align__(16) float g_y[TT * KTOP * HH];     // 32 MB  weighted expert outputs per slot
__device__ float g_slot_w[TT * KTOP];                   // routing weight per slot
__device__ int   g_expert_cnt[NE];
__device__ int   g_expert_slots[NE * TT];               // slot ids grouped by expert

// ---------------- kernel 0: zero expert counters ------------------------------
__global__ void zero_cnt_kernel() {
    if (threadIdx.x < NE) g_expert_cnt[threadIdx.x] = 0;
}

// ---------------- kernel 1: RMSNorm -------------------------------------------
__global__ void rmsnorm_kernel(const float* __restrict__ x,
                               const float* __restrict__ scale) {
    int t = blockIdx.x;
    const float* xr = x + (size_t)t * HH;
    float ss = 0.f;
    for (int h = threadIdx.x; h < HH; h += 256) {
        float v = xr[h];
        ss += v * v;
    }
    __shared__ float red[8];
    #pragma unroll
    for (int o = 16; o; o >>= 1) ss += __shfl_xor_sync(0xffffffffu, ss, o);
    if ((threadIdx.x & 31) == 0) red[threadIdx.x >> 5] = ss;
    __syncthreads();
    if (threadIdx.x < 8) {
        float v = red[threadIdx.x];
        #pragma unroll
        for (int o = 4; o; o >>= 1) v += __shfl_xor_sync(0xffu, v, o);
        if (threadIdx.x == 0) red[0] = v;
    }
    __syncthreads();
    float rms = rsqrtf(red[0] * (1.0f / HH) + EPSF);
    for (int h = threadIdx.x; h < HH; h += 256)
        g_t[(size_t)t * HH + h] = xr[h] * rms * scale[h];
}

// ---------------- kernel 2: gate GEMV + top4 + softmax + routing lists --------
__global__ void gate_kernel(const float* __restrict__ gate_w,
                            const float* __restrict__ gate_b) {
    int t = blockIdx.x;
    __shared__ float ts[HH];
    __shared__ float gv[NE];
    for (int h = threadIdx.x; h < HH; h += 256) ts[h] = g_t[(size_t)t * HH + h];
    __syncthreads();

    int g = threadIdx.x >> 4;   // expert 0..15
    int j = threadIdx.x & 15;
    const float* wr = gate_w + g * HH;
    float sum = 0.f;
    for (int h = j; h < HH; h += 16) sum += ts[h] * wr[h];
    #pragma unroll
    for (int o = 8; o; o >>= 1) sum += __shfl_xor_sync(0xffffffffu, sum, o);
    if (j == 0) gv[g] = sum + gate_b[g];
    __syncthreads();

    if (threadIdx.x == 0) {
        float vals[KTOP];
        int   idx[KTOP];
        bool  used[NE];
        #pragma unroll
        for (int e = 0; e < NE; e++) used[e] = false;
        #pragma unroll
        for (int k = 0; k < KTOP; k++) {
            float best = -INFINITY; int bi = 0;
            for (int e = 0; e < NE; e++)
                if (!used[e] && gv[e] > best) { best = gv[e]; bi = e; }
            used[bi] = true; vals[k] = best; idx[k] = bi;
        }
        float m = vals[0];
        float se = 0.f, w[KTOP];
        #pragma unroll
        for (int k = 0; k < KTOP; k++) { w[k] = __expf(vals[k] - m); se += w[k]; }
        float inv = 1.0f / se;
        #pragma unroll
        for (int k = 0; k < KTOP; k++) {
            int slot = t * KTOP + k;
            g_slot_w[slot] = w[k] * inv;
            int pos = atomicAdd(&g_expert_cnt[idx[k]], 1);
            g_expert_slots[idx[k] * TT + pos] = slot;
        }
    }
}

// ---------------- kernel 3: GEMM1 (even rows only) + bias + swiglu ------------
// s[slot, n] = swiglu( sum_h t[token,h] * w1[e, 2n, h] + b1[e, 2n] )
__global__ void __launch_bounds__(256) mlp1_kernel(const float* __restrict__ w1,
                                                   const float* __restrict__ b1) {
    int e = blockIdx.z;
    int cnt = g_expert_cnt[e];
    int mt = blockIdx.y;
    if (mt * BM >= cnt) return;
    int nt = blockIdx.x;

    __shared__ float As[BK][BM + 4];
    __shared__ float Bs[BK][BN + 4];
    __shared__ int slots[BM];

    int tid = threadIdx.x;
    if (tid < BM) {
        int idx = mt * BM + tid;
        slots[tid] = (idx < cnt) ? g_expert_slots[e * TT + idx] : -1;
    }
    __syncthreads();

    int tx = tid & 15, ty = tid >> 4;
    float acc[4][4] = {};

    const float* w1e = w1 + (size_t)e * (2 * II) * HH;
    int lr = tid >> 2;          // 0..63
    int lk = (tid & 3) * 4;     // 0,4,8,12
    int aslot = slots[lr];
    const float* arow = (aslot >= 0) ? (g_t + (size_t)(aslot >> 2) * HH) : g_t;
    const float* brow = w1e + (size_t)(2 * (nt * BN + lr)) * HH;   // even row

    for (int kb = 0; kb < HH; kb += BK) {
        float4 av = (aslot >= 0) ? *(const float4*)(arow + kb + lk)
                                 : make_float4(0.f, 0.f, 0.f, 0.f);
        float4 bv = *(const float4*)(brow + kb + lk);
        As[lk + 0][lr] = av.x; As[lk + 1][lr] = av.y;
        As[lk + 2][lr] = av.z; As[lk + 3][lr] = av.w;
        Bs[lk + 0][lr] = bv.x; Bs[lk + 1][lr] = bv.y;
        Bs[lk + 2][lr] = bv.z; Bs[lk + 3][lr] = bv.w;
        __syncthreads();
        #pragma unroll
        for (int kk = 0; kk < BK; kk++) {
            float4 a = *(const float4*)&As[kk][ty * 4];
            float4 b = *(const float4*)&Bs[kk][tx * 4];
            acc[0][0] += a.x * b.x; acc[0][1] += a.x * b.y;
            acc[0][2] += a.x * b.z; acc[0][3] += a.x * b.w;
            acc[1][0] += a.y * b.x; acc[1][1] += a.y * b.y;
            acc[1][2] += a.y * b.z; acc[1][3] += a.y * b.w;
            acc[2][0] += a.z * b.x; acc[2][1] += a.z * b.y;
            acc[2][2] += a.z * b.z; acc[2][3] += a.z * b.w;
            acc[3][0] += a.w * b.x; acc[3][1] += a.w * b.y;
            acc[3][2] += a.w * b.z; acc[3][3] += a.w * b.w;
        }
        __syncthreads();
    }

    #pragma unroll
    for (int i2 = 0; i2 < 4; i2++) {
        int m = ty * 4 + i2;
        int slot = slots[m];
        if (slot < 0) continue;
        #pragma unroll
        for (int j2 = 0; j2 < 4; j2++) {
            int n = nt * BN + tx * 4 + j2;
            float hsum = acc[i2][j2] + b1[e * (2 * II) + 2 * n];
            float gl = fminf(hsum, LIMITF);
            // x_lin = clip(h_odd,7,7) == 7 exactly -> (x_lin + 1) == 8
            float sig = 1.0f / (1.0f + __expf(-ALPHAF * gl));
            g_s[(size_t)slot * II + n] = gl * sig * (LIMITF + 1.0f);
        }
    }
}

// ---------------- kernel 4: GEMM2 + bias, scaled by routing weight ------------
// y[slot, n] = w_slot * ( sum_i s[slot,i] * w2[e, n, i] + b2[e, n] )
__global__ void __launch_bounds__(256) mlp2_kernel(const float* __restrict__ w2,
                                                   const float* __restrict__ b2) {
    int e = blockIdx.z;
    int cnt = g_expert_cnt[e];
    int mt = blockIdx.y;
    if (mt * BM >= cnt) return;
    int nt = blockIdx.x;

    __shared__ float As[BK][BM + 4];
    __shared__ float Bs[BK][BN + 4];
    __shared__ int slots[BM];

    int tid = threadIdx.x;
    if (tid < BM) {
        int idx = mt * BM + tid;
        slots[tid] = (idx < cnt) ? g_expert_slots[e * TT + idx] : -1;
    }
    __syncthreads();

    int tx = tid & 15, ty = tid >> 4;
    float acc[4][4] = {};

    const float* w2e = w2 + (size_t)e * HH * II;
    int lr = tid >> 2;
    int lk = (tid & 3) * 4;
    int aslot = slots[lr];
    const float* arow = (aslot >= 0) ? (g_s + (size_t)aslot * II) : g_s;
    const float* brow = w2e + (size_t)(nt * BN + lr) * II;

    for (int kb = 0; kb < II; kb += BK) {
        float4 av = (aslot >= 0) ? *(const float4*)(arow + kb + lk)
                                 : make_float4(0.f, 0.f, 0.f, 0.f);
        float4 bv = *(const float4*)(brow + kb + lk);
        As[lk + 0][lr] = av.x; As[lk + 1][lr] = av.y;
        As[lk + 2][lr] = av.z; As[lk + 3][lr] = av.w;
        Bs[lk + 0][lr] = bv.x; Bs[lk + 1][lr] = bv.y;
        Bs[lk + 2][lr] = bv.z; Bs[lk + 3][lr] = bv.w;
        __syncthreads();
        #pragma unroll
        for (int kk = 0; kk < BK; kk++) {
            float4 a = *(const float4*)&As[kk][ty * 4];
            float4 b = *(const float4*)&Bs[kk][tx * 4];
            acc[0][0] += a.x * b.x; acc[0][1] += a.x * b.y;
            acc[0][2] += a.x * b.z; acc[0][3] += a.x * b.w;
            acc[1][0] += a.y * b.x; acc[1][1] += a.y * b.y;
            acc[1][2] += a.y * b.z; acc[1][3] += a.y * b.w;
            acc[2][0] += a.z * b.x; acc[2][1] += a.z * b.y;
            acc[2][2] += a.z * b.z; acc[2][3] += a.z * b.w;
            acc[3][0] += a.w * b.x; acc[3][1] += a.w * b.y;
            acc[3][2] += a.w * b.z; acc[3][3] += a.w * b.w;
        }
        __syncthreads();
    }

    #pragma unroll
    for (int i2 = 0; i2 < 4; i2++) {
        int m = ty * 4 + i2;
        int slot = slots[m];
        if (slot < 0) continue;
        float rw = g_slot_w[slot];
        #pragma unroll
        for (int j2 = 0; j2 < 4; j2++) {
            int n = nt * BN + tx * 4 + j2;
            float y = (acc[i2][j2] + b2[e * HH + n]) * rw;
            g_y[(size_t)slot * HH + n] = y;
        }
    }
}

// ---------------- kernel 5: out = x + sum_k y[t*4+k] --------------------------
__global__ void finalize_kernel(const float* __restrict__ x,
                                float* __restrict__ out) {
    int idx = blockIdx.x * 256 + threadIdx.x;
    int t = idx >> 10;
    int h = idx & 1023;
    float v = x[idx];
    size_t base = (size_t)t * KTOP * HH + h;
    v += g_y[base];
    v += g_y[base + HH];
    v += g_y[base + 2 * HH];
    v += g_y[base + 3 * HH];
    out[idx] = v;
}

// ---------------- launcher -----------------------------------------------------
extern "C" void kernel_launch(void* const* d_in, const int* in_sizes, int n_in,
                              void* d_out, int out_size) {
    const float* x      = (const float*)d_in[0];
    const float* scale  = (const float*)d_in[1];
    const float* gate_w = (const float*)d_in[2];
    const float* gate_b = (const float*)d_in[3];
    const float* w1     = (const float*)d_in[4];
    const float* b1     = (const float*)d_in[5];
    const float* w2     = (const float*)d_in[6];
    const float* b2     = (const float*)d_in[7];
    float* out = (float*)d_out;

    zero_cnt_kernel<<<1, 32>>>();
    rmsnorm_kernel<<<TT, 256>>>(x, scale);
    gate_kernel<<<TT, 256>>>(gate_w, gate_b);

    dim3 g1(II / BN, TT / BM, NE);   // (16, 32, 16) — blocks early-exit past cnt
    mlp1_kernel<<<g1, 256>>>(w1, b1);

    dim3 g2(HH / BN, TT / BM, NE);
    mlp2_kernel<<<g2, 256>>>(w2, b2);

    finalize_kernel<<<(TT * HH) / 256, 256>>>(x, out);
}

// round 3
// speedup vs baseline: 2.7652x; 2.7652x over previous
#include <cuda_runtime.h>
#include <math.h>

#define TT 2048
#define HH 1024
#define II 1024
#define NE 16
#define KTOP 4
#define EPSF 1e-5f
#define ALPHAF 1.702f
#define LIMITF 7.0f

#define BM 128
#define BN 128
#define BK 16
#define PAD 20          // floats per smem row (16 + 4 pad) -> conflict-free

// ---------------- scratch (static device globals; no allocation) -------------
__device__ __align__(16) float g_t[TT * HH];            // 8 MB   rmsnorm output
__device__ __align__(16) float g_s[TT * KTOP * II];     // 32 MB  swiglu activations per slot
__device__ __align__(16) float g_y[TT * KTOP * HH];     // 32 MB  weighted expert outputs per slot
__device__ float g_slot_w[TT * KTOP];
__device__ int   g_expert_cnt[NE];
__device__ int   g_expert_slots[NE * TT];

// ---------------- helpers ------------------------------------------------------
__device__ __forceinline__ unsigned f2tf(float f) {
    unsigned r;
    asm("cvt.rna.tf32.f32 %0, %1;" : "=r"(r) : "f"(f));
    return r;
}

__device__ __forceinline__ void mma_tf32(float* d, const unsigned* a, const unsigned* b) {
    asm volatile(
        "mma.sync.aligned.m16n8k8.row.col.f32.tf32.tf32.f32 "
        "{%0,%1,%2,%3}, {%4,%5,%6,%7}, {%8,%9}, {%0,%1,%2,%3};"
        : "+f"(d[0]), "+f"(d[1]), "+f"(d[2]), "+f"(d[3])
        : "r"(a[0]), "r"(a[1]), "r"(a[2]), "r"(a[3]), "r"(b[0]), "r"(b[1]));
}

// ---------------- kernel 0: zero expert counters ------------------------------
__global__ void zero_cnt_kernel() {
    if (threadIdx.x < NE) g_expert_cnt[threadIdx.x] = 0;
}

// ---------------- kernel 1: RMSNorm -------------------------------------------
__global__ void rmsnorm_kernel(const float* __restrict__ x,
                               const float* __restrict__ scale) {
    int t = blockIdx.x;
    const float* xr = x + (size_t)t * HH;
    float ss = 0.f;
    for (int h = threadIdx.x; h < HH; h += 256) {
        float v = xr[h];
        ss += v * v;
    }
    __shared__ float red[8];
    #pragma unroll
    for (int o = 16; o; o >>= 1) ss += __shfl_xor_sync(0xffffffffu, ss, o);
    if ((threadIdx.x & 31) == 0) red[threadIdx.x >> 5] = ss;
    __syncthreads();
    if (threadIdx.x < 8) {
        float v = red[threadIdx.x];
        #pragma unroll
        for (int o = 4; o; o >>= 1) v += __shfl_xor_sync(0xffu, v, o);
        if (threadIdx.x == 0) red[0] = v;
    }
    __syncthreads();
    float rms = rsqrtf(red[0] * (1.0f / HH) + EPSF);
    for (int h = threadIdx.x; h < HH; h += 256)
        g_t[(size_t)t * HH + h] = xr[h] * rms * scale[h];
}

// ---------------- kernel 2: gate GEMV + top4 + softmax + routing lists --------
__global__ void gate_kernel(const float* __restrict__ gate_w,
                            const float* __restrict__ gate_b) {
    int t = blockIdx.x;
    __shared__ float ts[HH];
    __shared__ float gv[NE];
    for (int h = threadIdx.x; h < HH; h += 256) ts[h] = g_t[(size_t)t * HH + h];
    __syncthreads();

    int g = threadIdx.x >> 4;
    int j = threadIdx.x & 15;
    const float* wr = gate_w + g * HH;
    float sum = 0.f;
    for (int h = j; h < HH; h += 16) sum += ts[h] * wr[h];
    #pragma unroll
    for (int o = 8; o; o >>= 1) sum += __shfl_xor_sync(0xffffffffu, sum, o);
    if (j == 0) gv[g] = sum + gate_b[g];
    __syncthreads();

    if (threadIdx.x == 0) {
        float vals[KTOP];
        int   idx[KTOP];
        bool  used[NE];
        #pragma unroll
        for (int e = 0; e < NE; e++) used[e] = false;
        #pragma unroll
        for (int k = 0; k < KTOP; k++) {
            float best = -INFINITY; int bi = 0;
            for (int e = 0; e < NE; e++)
                if (!used[e] && gv[e] > best) { best = gv[e]; bi = e; }
            used[bi] = true; vals[k] = best; idx[k] = bi;
        }
        float m = vals[0];
        float se = 0.f, w[KTOP];
        #pragma unroll
        for (int k = 0; k < KTOP; k++) { w[k] = __expf(vals[k] - m); se += w[k]; }
        float inv = 1.0f / se;
        #pragma unroll
        for (int k = 0; k < KTOP; k++) {
            int slot = t * KTOP + k;
            g_slot_w[slot] = w[k] * inv;
            int pos = atomicAdd(&g_expert_cnt[idx[k]], 1);
            g_expert_slots[idx[k] * TT + pos] = slot;
        }
    }
}

// ================= tf32 tensor-core GEMM kernels ===============================
// 128x128x16 tiles, double buffered. 8 warps (4 m x 2 n), each warp 32x64
// via 2x8 m16n8k8 mma tiles.

// ---------------- kernel 3: GEMM1 (even w1 rows) + bias + swiglu --------------
__global__ void __launch_bounds__(256, 2) mlp1_kernel(const float* __restrict__ w1,
                                                      const float* __restrict__ b1) {
    int e = blockIdx.z;
    int cnt = g_expert_cnt[e];
    int mt = blockIdx.y;
    if (mt * BM >= cnt) return;
    int nt = blockIdx.x;
    int ntB = nt * BN;

    __shared__ unsigned As[2][BM][PAD];
    __shared__ unsigned Bs[2][BN][PAD];
    __shared__ int slots[BM];

    int tid = threadIdx.x;
    if (tid < BM) {
        int idx = mt * BM + tid;
        slots[tid] = (idx < cnt) ? g_expert_slots[e * TT + idx] : -1;
    }
    __syncthreads();

    int wid = tid >> 5;
    int lane = tid & 31;
    int wm = wid & 3;            // warp row 0..3  (32 rows each)
    int wn = wid >> 2;           // warp col 0..1  (64 cols each)
    int grp = lane >> 2;         // 0..7
    int tig = lane & 3;          // 0..3

    // gmem staging assignment: thread covers float4 idx tid and tid+256
    int m0 = tid >> 2;           // row 0..63
    int m1 = m0 + 64;            // row 64..127
    int kq = (tid & 3) * 4;      // k offset 0,4,8,12

    const float* w1e = w1 + (size_t)e * (2 * II) * HH;
    int s0 = slots[m0], s1 = slots[m1];
    const float* aptr0 = g_t + (size_t)((s0 >= 0 ? (s0 >> 2) : 0)) * HH + kq;
    const float* aptr1 = g_t + (size_t)((s1 >= 0 ? (s1 >> 2) : 0)) * HH + kq;
    const float* bptr0 = w1e + (size_t)(2 * (ntB + m0)) * HH + kq;
    const float* bptr1 = w1e + (size_t)(2 * (ntB + m1)) * HH + kq;

    float acc[2][8][4];
    #pragma unroll
    for (int i = 0; i < 2; i++)
        #pragma unroll
        for (int j = 0; j < 8; j++)
            #pragma unroll
            for (int c = 0; c < 4; c++) acc[i][j][c] = 0.f;

    // prologue: stage k-tile 0
    float4 av0 = *(const float4*)(aptr0);
    float4 av1 = *(const float4*)(aptr1);
    float4 bv0 = *(const float4*)(bptr0);
    float4 bv1 = *(const float4*)(bptr1);
    {
        uint4 u;
        u.x = f2tf(av0.x); u.y = f2tf(av0.y); u.z = f2tf(av0.z); u.w = f2tf(av0.w);
        *(uint4*)&As[0][m0][kq] = u;
        u.x = f2tf(av1.x); u.y = f2tf(av1.y); u.z = f2tf(av1.z); u.w = f2tf(av1.w);
        *(uint4*)&As[0][m1][kq] = u;
        u.x = f2tf(bv0.x); u.y = f2tf(bv0.y); u.z = f2tf(bv0.z); u.w = f2tf(bv0.w);
        *(uint4*)&Bs[0][m0][kq] = u;
        u.x = f2tf(bv1.x); u.y = f2tf(bv1.y); u.z = f2tf(bv1.z); u.w = f2tf(bv1.w);
        *(uint4*)&Bs[0][m1][kq] = u;
    }
    __syncthreads();

    const int NKT = HH / BK;     // 64
    for (int kb = 0; kb < NKT; kb++) {
        int cur = kb & 1;
        if (kb + 1 < NKT) {
            int ko = (kb + 1) * BK;
            av0 = *(const float4*)(aptr0 + ko);
            av1 = *(const float4*)(aptr1 + ko);
            bv0 = *(const float4*)(bptr0 + ko);
            bv1 = *(const float4*)(bptr1 + ko);
        }
        #pragma unroll
        for (int ks = 0; ks < 2; ks++) {
            int k0 = ks * 8;
            unsigned a[2][4], b[8][2];
            #pragma unroll
            for (int sm = 0; sm < 2; sm++) {
                int r = wm * 32 + sm * 16 + grp;
                a[sm][0] = As[cur][r][k0 + tig];
                a[sm][1] = As[cur][r + 8][k0 + tig];
                a[sm][2] = As[cur][r][k0 + tig + 4];
                a[sm][3] = As[cur][r + 8][k0 + tig + 4];
            }
            #pragma unroll
            for (int sn = 0; sn < 8; sn++) {
                int c = wn * 64 + sn * 8 + grp;
                b[sn][0] = Bs[cur][c][k0 + tig];
                b[sn][1] = Bs[cur][c][k0 + tig + 4];
            }
            #pragma unroll
            for (int sm = 0; sm < 2; sm++)
                #pragma unroll
                for (int sn = 0; sn < 8; sn++)
                    mma_tf32(acc[sm][sn], a[sm], b[sn]);
        }
        if (kb + 1 < NKT) {
            int nxt = cur ^ 1;
            uint4 u;
            u.x = f2tf(av0.x); u.y = f2tf(av0.y); u.z = f2tf(av0.z); u.w = f2tf(av0.w);
            *(uint4*)&As[nxt][m0][kq] = u;
            u.x = f2tf(av1.x); u.y = f2tf(av1.y); u.z = f2tf(av1.z); u.w = f2tf(av1.w);
            *(uint4*)&As[nxt][m1][kq] = u;
            u.x = f2tf(bv0.x); u.y = f2tf(bv0.y); u.z = f2tf(bv0.z); u.w = f2tf(bv0.w);
            *(uint4*)&Bs[nxt][m0][kq] = u;
            u.x = f2tf(bv1.x); u.y = f2tf(bv1.y); u.z = f2tf(bv1.z); u.w = f2tf(bv1.w);
            *(uint4*)&Bs[nxt][m1][kq] = u;
        }
        __syncthreads();
    }

    // epilogue: bias + swiglu (odd half of mlp1 is constant LIMIT -> *8)
    const float* b1e = b1 + e * (2 * II);
    #pragma unroll
    for (int sm = 0; sm < 2; sm++) {
        int rbase = wm * 32 + sm * 16 + grp;
        #pragma unroll
        for (int half = 0; half < 2; half++) {
            int row = rbase + half * 8;
            int slot = slots[row];
            if (slot < 0) continue;
            float* srow = g_s + (size_t)slot * II;
            #pragma unroll
            for (int sn = 0; sn < 8; sn++) {
                int n = ntB + wn * 64 + sn * 8 + 2 * tig;
                #pragma unroll
                for (int cc = 0; cc < 2; cc++) {
                    float hsum = acc[sm][sn][half * 2 + cc] + b1e[2 * (n + cc)];
                    float gl = fminf(hsum, LIMITF);
                    float sig = 1.0f / (1.0f + __expf(-ALPHAF * gl));
                    srow[n + cc] = gl * sig * (LIMITF + 1.0f);
                }
            }
        }
    }
}

// ---------------- kernel 4: GEMM2 + bias, scaled by routing weight ------------
__global__ void __launch_bounds__(256, 2) mlp2_kernel(const float* __restrict__ w2,
                                                      const float* __restrict__ b2) {
    int e = blockIdx.z;
    int cnt = g_expert_cnt[e];
    int mt = blockIdx.y;
    if (mt * BM >= cnt) return;
    int nt = blockIdx.x;
    int ntB = nt * BN;

    __shared__ unsigned As[2][BM][PAD];
    __shared__ unsigned Bs[2][BN][PAD];
    __shared__ int slots[BM];

    int tid = threadIdx.x;
    if (tid < BM) {
        int idx = mt * BM + tid;
        slots[tid] = (idx < cnt) ? g_expert_slots[e * TT + idx] : -1;
    }
    __syncthreads();

    int wid = tid >> 5;
    int lane = tid & 31;
    int wm = wid & 3;
    int wn = wid >> 2;
    int grp = lane >> 2;
    int tig = lane & 3;

    int m0 = tid >> 2;
    int m1 = m0 + 64;
    int kq = (tid & 3) * 4;

    const float* w2e = w2 + (size_t)e * HH * II;
    int s0 = slots[m0], s1 = slots[m1];
    const float* aptr0 = g_s + (size_t)(s0 >= 0 ? s0 : 0) * II + kq;
    const float* aptr1 = g_s + (size_t)(s1 >= 0 ? s1 : 0) * II + kq;
    const float* bptr0 = w2e + (size_t)(ntB + m0) * II + kq;
    const float* bptr1 = w2e + (size_t)(ntB + m1) * II + kq;

    float acc[2][8][4];
    #pragma unroll
    for (int i = 0; i < 2; i++)
        #pragma unroll
        for (int j = 0; j < 8; j++)
            #pragma unroll
            for (int c = 0; c < 4; c++) acc[i][j][c] = 0.f;

    float4 av0 = *(const float4*)(aptr0);
    float4 av1 = *(const float4*)(aptr1);
    float4 bv0 = *(const float4*)(bptr0);
    float4 bv1 = *(const float4*)(bptr1);
    {
        uint4 u;
        u.x = f2tf(av0.x); u.y = f2tf(av0.y); u.z = f2tf(av0.z); u.w = f2tf(av0.w);
        *(uint4*)&As[0][m0][kq] = u;
        u.x = f2tf(av1.x); u.y = f2tf(av1.y); u.z = f2tf(av1.z); u.w = f2tf(av1.w);
        *(uint4*)&As[0][m1][kq] = u;
        u.x = f2tf(bv0.x); u.y = f2tf(bv0.y); u.z = f2tf(bv0.z); u.w = f2tf(bv0.w);
        *(uint4*)&Bs[0][m0][kq] = u;
        u.x = f2tf(bv1.x); u.y = f2tf(bv1.y); u.z = f2tf(bv1.z); u.w = f2tf(bv1.w);
        *(uint4*)&Bs[0][m1][kq] = u;
    }
    __syncthreads();

    const int NKT = II / BK;
    for (int kb = 0; kb < NKT; kb++) {
        int cur = kb & 1;
        if (kb + 1 < NKT) {
            int ko = (kb + 1) * BK;
            av0 = *(const float4*)(aptr0 + ko);
            av1 = *(const float4*)(aptr1 + ko);
            bv0 = *(const float4*)(bptr0 + ko);
            bv1 = *(const float4*)(bptr1 + ko);
        }
        #pragma unroll
        for (int ks = 0; ks < 2; ks++) {
            int k0 = ks * 8;
            unsigned a[2][4], b[8][2];
            #pragma unroll
            for (int sm = 0; sm < 2; sm++) {
                int r = wm * 32 + sm * 16 + grp;
                a[sm][0] = As[cur][r][k0 + tig];
                a[sm][1] = As[cur][r + 8][k0 + tig];
                a[sm][2] = As[cur][r][k0 + tig + 4];
                a[sm][3] = As[cur][r + 8][k0 + tig + 4];
            }
            #pragma unroll
            for (int sn = 0; sn < 8; sn++) {
                int c = wn * 64 + sn * 8 + grp;
                b[sn][0] = Bs[cur][c][k0 + tig];
                b[sn][1] = Bs[cur][c][k0 + tig + 4];
            }
            #pragma unroll
            for (int sm = 0; sm < 2; sm++)
                #pragma unroll
                for (int sn = 0; sn < 8; sn++)
                    mma_tf32(acc[sm][sn], a[sm], b[sn]);
        }
        if (kb + 1 < NKT) {
            int nxt = cur ^ 1;
            uint4 u;
            u.x = f2tf(av0.x); u.y = f2tf(av0.y); u.z = f2tf(av0.z); u.w = f2tf(av0.w);
            *(uint4*)&As[nxt][m0][kq] = u;
            u.x = f2tf(av1.x); u.y = f2tf(av1.y); u.z = f2tf(av1.z); u.w = f2tf(av1.w);
            *(uint4*)&As[nxt][m1][kq] = u;
            u.x = f2tf(bv0.x); u.y = f2tf(bv0.y); u.z = f2tf(bv0.z); u.w = f2tf(bv0.w);
            *(uint4*)&Bs[nxt][m0][kq] = u;
            u.x = f2tf(bv1.x); u.y = f2tf(bv1.y); u.z = f2tf(bv1.z); u.w = f2tf(bv1.w);
            *(uint4*)&Bs[nxt][m1][kq] = u;
        }
        __syncthreads();
    }

    const float* b2e = b2 + e * HH;
    #pragma unroll
    for (int sm = 0; sm < 2; sm++) {
        int rbase = wm * 32 + sm * 16 + grp;
        #pragma unroll
        for (int half = 0; half < 2; half++) {
            int row = rbase + half * 8;
            int slot = slots[row];
            if (slot < 0) continue;
            float rw = g_slot_w[slot];
            float* yrow = g_y + (size_t)slot * HH;
            #pragma unroll
            for (int sn = 0; sn < 8; sn++) {
                int n = ntB + wn * 64 + sn * 8 + 2 * tig;
                #pragma unroll
                for (int cc = 0; cc < 2; cc++) {
                    float y = (acc[sm][sn][half * 2 + cc] + b2e[n + cc]) * rw;
                    yrow[n + cc] = y;
                }
            }
        }
    }
}

// ---------------- kernel 5: out = x + sum_k y[t*4+k] --------------------------
__global__ void finalize_kernel(const float* __restrict__ x,
                                float* __restrict__ out) {
    int idx = blockIdx.x * 256 + threadIdx.x;
    int t = idx >> 10;
    int h = idx & 1023;
    float v = x[idx];
    size_t base = (size_t)t * KTOP * HH + h;
    v += g_y[base];
    v += g_y[base + HH];
    v += g_y[base + 2 * HH];
    v += g_y[base + 3 * HH];
    out[idx] = v;
}

// ---------------- launcher -----------------------------------------------------
extern "C" void kernel_launch(void* const* d_in, const int* in_sizes, int n_in,
                              void* d_out, int out_size) {
    const float* x      = (const float*)d_in[0];
    const float* scale  = (const float*)d_in[1];
    const float* gate_w = (const float*)d_in[2];
    const float* gate_b = (const float*)d_in[3];
    const float* w1     = (const float*)d_in[4];
    const float* b1     = (const float*)d_in[5];
    const float* w2     = (const float*)d_in[6];
    const float* b2     = (const float*)d_in[7];
    float* out = (float*)d_out;

    zero_cnt_kernel<<<1, 32>>>();
    rmsnorm_kernel<<<TT, 256>>>(x, scale);
    gate_kernel<<<TT, 256>>>(gate_w, gate_b);

    dim3 g1(II / BN, TT / BM, NE);   // (8, 16, 16) — blocks early-exit past cnt
    mlp1_kernel<<<g1, 256>>>(w1, b1);

    dim3 g2(HH / BN, TT / BM, NE);
    mlp2_kernel<<<g2, 256>>>(w2, b2);

    finalize_kernel<<<(TT * HH) / 256, 256>>>(x, out);
}

// round 4
// speedup vs baseline: 3.1858x; 1.1521x over previous
#include <cuda_runtime.h>
#include <math.h>

#define TT 2048
#define HH 1024
#define II 1024
#define NE 16
#define KTOP 4
#define EPSF 1e-5f
#define ALPHAF 1.702f
#define LIMITF 7.0f

#define BM 128
#define BN 128
#define BK 16
#define PAD 20          // 16 + 4 pad words per row -> conflict-free LDSM

// ---------------- scratch (static device globals; no allocation) -------------
__device__ __align__(16) float g_t[TT * HH];
__device__ __align__(16) float g_s[TT * KTOP * II];
__device__ __align__(16) float g_y[TT * KTOP * HH];
__device__ float g_slot_w[TT * KTOP];
__device__ int   g_expert_cnt[NE];
__device__ int   g_expert_slots[NE * TT];

// ---------------- helpers ------------------------------------------------------
__device__ __forceinline__ unsigned f2tf(float f) {
    unsigned r;
    asm("cvt.rna.tf32.f32 %0, %1;" : "=r"(r) : "f"(f));
    return r;
}

__device__ __forceinline__ void mma_tf32(float* d, const unsigned* a, const unsigned* b) {
    asm volatile(
        "mma.sync.aligned.m16n8k8.row.col.f32.tf32.tf32.f32 "
        "{%0,%1,%2,%3}, {%4,%5,%6,%7}, {%8,%9}, {%0,%1,%2,%3};"
        : "+f"(d[0]), "+f"(d[1]), "+f"(d[2]), "+f"(d[3])
        : "r"(a[0]), "r"(a[1]), "r"(a[2]), "r"(a[3]), "r"(b[0]), "r"(b[1]));
}

__device__ __forceinline__ void ldsm4(unsigned* r, unsigned addr) {
    asm volatile("ldmatrix.sync.aligned.m8n8.x4.shared.b16 {%0,%1,%2,%3}, [%4];"
        : "=r"(r[0]), "=r"(r[1]), "=r"(r[2]), "=r"(r[3]) : "r"(addr));
}

// ---------------- kernel 0 -----------------------------------------------------
__global__ void zero_cnt_kernel() {
    if (threadIdx.x < NE) g_expert_cnt[threadIdx.x] = 0;
}

// ---------------- kernel 1: RMSNorm -------------------------------------------
__global__ void rmsnorm_kernel(const float* __restrict__ x,
                               const float* __restrict__ scale) {
    int t = blockIdx.x;
    const float* xr = x + (size_t)t * HH;
    float ss = 0.f;
    for (int h = threadIdx.x; h < HH; h += 256) {
        float v = xr[h];
        ss += v * v;
    }
    __shared__ float red[8];
    #pragma unroll
    for (int o = 16; o; o >>= 1) ss += __shfl_xor_sync(0xffffffffu, ss, o);
    if ((threadIdx.x & 31) == 0) red[threadIdx.x >> 5] = ss;
    __syncthreads();
    if (threadIdx.x < 8) {
        float v = red[threadIdx.x];
        #pragma unroll
        for (int o = 4; o; o >>= 1) v += __shfl_xor_sync(0xffu, v, o);
        if (threadIdx.x == 0) red[0] = v;
    }
    __syncthreads();
    float rms = rsqrtf(red[0] * (1.0f / HH) + EPSF);
    for (int h = threadIdx.x; h < HH; h += 256)
        g_t[(size_t)t * HH + h] = xr[h] * rms * scale[h];
}

// ---------------- kernel 2: gate + top4 + routing -----------------------------
__global__ void gate_kernel(const float* __restrict__ gate_w,
                            const float* __restrict__ gate_b) {
    int t = blockIdx.x;
    __shared__ float ts[HH];
    __shared__ float gv[NE];
    for (int h = threadIdx.x; h < HH; h += 256) ts[h] = g_t[(size_t)t * HH + h];
    __syncthreads();

    int g = threadIdx.x >> 4;
    int j = threadIdx.x & 15;
    const float* wr = gate_w + g * HH;
    float sum = 0.f;
    for (int h = j; h < HH; h += 16) sum += ts[h] * wr[h];
    #pragma unroll
    for (int o = 8; o; o >>= 1) sum += __shfl_xor_sync(0xffffffffu, sum, o);
    if (j == 0) gv[g] = sum + gate_b[g];
    __syncthreads();

    if (threadIdx.x == 0) {
        float vals[KTOP];
        int   idx[KTOP];
        bool  used[NE];
        #pragma unroll
        for (int e = 0; e < NE; e++) used[e] = false;
        #pragma unroll
        for (int k = 0; k < KTOP; k++) {
            float best = -INFINITY; int bi = 0;
            for (int e = 0; e < NE; e++)
                if (!used[e] && gv[e] > best) { best = gv[e]; bi = e; }
            used[bi] = true; vals[k] = best; idx[k] = bi;
        }
        float m = vals[0];
        float se = 0.f, w[KTOP];
        #pragma unroll
        for (int k = 0; k < KTOP; k++) { w[k] = __expf(vals[k] - m); se += w[k]; }
        float inv = 1.0f / se;
        #pragma unroll
        for (int k = 0; k < KTOP; k++) {
            int slot = t * KTOP + k;
            g_slot_w[slot] = w[k] * inv;
            int pos = atomicAdd(&g_expert_cnt[idx[k]], 1);
            g_expert_slots[idx[k] * TT + pos] = slot;
        }
    }
}

// ================= tf32 GEMMs: 128x128 block, 4 warps, 64x64 warp tile ========
// ldmatrix fragment loads; double-buffered smem; 2 CTAs/SM.

// ---------------- kernel 3: GEMM1 (even w1 rows) + bias + swiglu --------------
__global__ void __launch_bounds__(128, 2) mlp1_kernel(const float* __restrict__ w1,
                                                      const float* __restrict__ b1) {
    int e = blockIdx.z;
    int cnt = g_expert_cnt[e];
    int mt = blockIdx.y;
    if (mt * BM >= cnt) return;
    int ntB = blockIdx.x * BN;

    __shared__ __align__(16) unsigned As[2][BM][PAD];
    __shared__ __align__(16) unsigned Bs[2][BN][PAD];
    __shared__ int slots[BM];

    int tid = threadIdx.x;
    {
        int idx = mt * BM + tid;
        slots[tid] = (idx < cnt) ? g_expert_slots[e * TT + idx] : -1;
    }
    __syncthreads();

    int lane = tid & 31, wid = tid >> 5;
    int wm = wid & 1, wn = wid >> 1;        // 2m x 2n warps, 64x64 each
    int grp = lane >> 2, tig = lane & 3;
    int rA = (lane & 7) + (((lane >> 3) & 1) << 3);
    int kA = (lane >> 4) << 2;
    int rB = (lane & 7) + ((lane >> 4) << 3);
    int kB = ((lane >> 3) & 1) << 2;
    unsigned aAddr = (unsigned)__cvta_generic_to_shared(&As[0][wm * 64 + rA][kA]);
    unsigned bAddr = (unsigned)__cvta_generic_to_shared(&Bs[0][wn * 64 + rB][kB]);

    // staging: thread covers rows sr+{0,32,64,96}, k-quad kq
    int sr = tid >> 2;
    int kq = (tid & 3) * 4;
    const float* w1e = w1 + (size_t)e * (2 * II) * HH;
    const float* aptr[4];
    const float* bptr[4];
    #pragma unroll
    for (int i = 0; i < 4; i++) {
        int row = sr + i * 32;
        int s = slots[row];
        aptr[i] = g_t + (size_t)((s >= 0) ? (s >> 2) : 0) * HH + kq;
        bptr[i] = w1e + (size_t)(2 * (ntB + row)) * HH + kq;
    }

    float acc[4][8][4] = {};
    float4 av[4], bv[4];

    #pragma unroll
    for (int i = 0; i < 4; i++) { av[i] = *(const float4*)(aptr[i]); bv[i] = *(const float4*)(bptr[i]); }
    #pragma unroll
    for (int i = 0; i < 4; i++) {
        int row = sr + i * 32;
        uint4 u;
        u.x = f2tf(av[i].x); u.y = f2tf(av[i].y); u.z = f2tf(av[i].z); u.w = f2tf(av[i].w);
        *(uint4*)&As[0][row][kq] = u;
        u.x = f2tf(bv[i].x); u.y = f2tf(bv[i].y); u.z = f2tf(bv[i].z); u.w = f2tf(bv[i].w);
        *(uint4*)&Bs[0][row][kq] = u;
    }
    __syncthreads();

    const int NKT = HH / BK;
    for (int kb = 0; kb < NKT; kb++) {
        int cur = kb & 1;
        if (kb + 1 < NKT) {
            int ko = (kb + 1) * BK;
            #pragma unroll
            for (int i = 0; i < 4; i++) {
                av[i] = *(const float4*)(aptr[i] + ko);
                bv[i] = *(const float4*)(bptr[i] + ko);
            }
        }
        unsigned aOff = aAddr + (unsigned)(cur * (BM * PAD * 4));
        unsigned bOff = bAddr + (unsigned)(cur * (BN * PAD * 4));
        #pragma unroll
        for (int ks = 0; ks < 2; ks++) {
            unsigned afr[4][4], bfr[4][4];
            #pragma unroll
            for (int sm = 0; sm < 4; sm++)
                ldsm4(afr[sm], aOff + (unsigned)((sm * 16 * PAD + ks * 8) * 4));
            #pragma unroll
            for (int p = 0; p < 4; p++)
                ldsm4(bfr[p], bOff + (unsigned)((p * 16 * PAD + ks * 8) * 4));
            #pragma unroll
            for (int sm = 0; sm < 4; sm++)
                #pragma unroll
                for (int sn = 0; sn < 8; sn++)
                    mma_tf32(acc[sm][sn], afr[sm], &bfr[sn >> 1][(sn & 1) * 2]);
        }
        if (kb + 1 < NKT) {
            int nxt = cur ^ 1;
            #pragma unroll
            for (int i = 0; i < 4; i++) {
                int row = sr + i * 32;
                uint4 u;
                u.x = f2tf(av[i].x); u.y = f2tf(av[i].y); u.z = f2tf(av[i].z); u.w = f2tf(av[i].w);
                *(uint4*)&As[nxt][row][kq] = u;
                u.x = f2tf(bv[i].x); u.y = f2tf(bv[i].y); u.z = f2tf(bv[i].z); u.w = f2tf(bv[i].w);
                *(uint4*)&Bs[nxt][row][kq] = u;
            }
        }
        __syncthreads();
    }

    const float* b1e = b1 + e * (2 * II);
    #pragma unroll
    for (int sm = 0; sm < 4; sm++) {
        int rbase = wm * 64 + sm * 16 + grp;
        #pragma unroll
        for (int half = 0; half < 2; half++) {
            int row = rbase + half * 8;
            int slot = slots[row];
            if (slot < 0) continue;
            float* srow = g_s + (size_t)slot * II;
            #pragma unroll
            for (int sn = 0; sn < 8; sn++) {
                int n = ntB + wn * 64 + sn * 8 + 2 * tig;
                #pragma unroll
                for (int cc = 0; cc < 2; cc++) {
                    float hsum = acc[sm][sn][half * 2 + cc] + b1e[2 * (n + cc)];
                    float gl = fminf(hsum, LIMITF);
                    float sig = 1.0f / (1.0f + __expf(-ALPHAF * gl));
                    srow[n + cc] = gl * sig * (LIMITF + 1.0f);
                }
            }
        }
    }
}

// ---------------- kernel 4: GEMM2 + bias, scaled by routing weight ------------
__global__ void __launch_bounds__(128, 2) mlp2_kernel(const float* __restrict__ w2,
                                                      const float* __restrict__ b2) {
    int e = blockIdx.z;
    int cnt = g_expert_cnt[e];
    int mt = blockIdx.y;
    if (mt * BM >= cnt) return;
    int ntB = blockIdx.x * BN;

    __shared__ __align__(16) unsigned As[2][BM][PAD];
    __shared__ __align__(16) unsigned Bs[2][BN][PAD];
    __shared__ int slots[BM];

    int tid = threadIdx.x;
    {
        int idx = mt * BM + tid;
        slots[tid] = (idx < cnt) ? g_expert_slots[e * TT + idx] : -1;
    }
    __syncthreads();

    int lane = tid & 31, wid = tid >> 5;
    int wm = wid & 1, wn = wid >> 1;
    int grp = lane >> 2, tig = lane & 3;
    int rA = (lane & 7) + (((lane >> 3) & 1) << 3);
    int kA = (lane >> 4) << 2;
    int rB = (lane & 7) + ((lane >> 4) << 3);
    int kB = ((lane >> 3) & 1) << 2;
    unsigned aAddr = (unsigned)__cvta_generic_to_shared(&As[0][wm * 64 + rA][kA]);
    unsigned bAddr = (unsigned)__cvta_generic_to_shared(&Bs[0][wn * 64 + rB][kB]);

    int sr = tid >> 2;
    int kq = (tid & 3) * 4;
    const float* w2e = w2 + (size_t)e * HH * II;
    const float* aptr[4];
    const float* bptr[4];
    #pragma unroll
    for (int i = 0; i < 4; i++) {
        int row = sr + i * 32;
        int s = slots[row];
        aptr[i] = g_s + (size_t)((s >= 0) ? s : 0) * II + kq;
        bptr[i] = w2e + (size_t)(ntB + row) * II + kq;
    }

    float acc[4][8][4] = {};
    float4 av[4], bv[4];

    #pragma unroll
    for (int i = 0; i < 4; i++) { av[i] = *(const float4*)(aptr[i]); bv[i] = *(const float4*)(bptr[i]); }
    #pragma unroll
    for (int i = 0; i < 4; i++) {
        int row = sr + i * 32;
        uint4 u;
        u.x = f2tf(av[i].x); u.y = f2tf(av[i].y); u.z = f2tf(av[i].z); u.w = f2tf(av[i].w);
        *(uint4*)&As[0][row][kq] = u;
        u.x = f2tf(bv[i].x); u.y = f2tf(bv[i].y); u.z = f2tf(bv[i].z); u.w = f2tf(bv[i].w);
        *(uint4*)&Bs[0][row][kq] = u;
    }
    __syncthreads();

    const int NKT = II / BK;
    for (int kb = 0; kb < NKT; kb++) {
        int cur = kb & 1;
        if (kb + 1 < NKT) {
            int ko = (kb + 1) * BK;
            #pragma unroll
            for (int i = 0; i < 4; i++) {
                av[i] = *(const float4*)(aptr[i] + ko);
                bv[i] = *(const float4*)(bptr[i] + ko);
            }
        }
        unsigned aOff = aAddr + (unsigned)(cur * (BM * PAD * 4));
        unsigned bOff = bAddr + (unsigned)(cur * (BN * PAD * 4));
        #pragma unroll
        for (int ks = 0; ks < 2; ks++) {
            unsigned afr[4][4], bfr[4][4];
            #pragma unroll
            for (int sm = 0; sm < 4; sm++)
                ldsm4(afr[sm], aOff + (unsigned)((sm * 16 * PAD + ks * 8) * 4));
            #pragma unroll
            for (int p = 0; p < 4; p++)
                ldsm4(bfr[p], bOff + (unsigned)((p * 16 * PAD + ks * 8) * 4));
            #pragma unroll
            for (int sm = 0; sm < 4; sm++)
                #pragma unroll
                for (int sn = 0; sn < 8; sn++)
                    mma_tf32(acc[sm][sn], afr[sm], &bfr[sn >> 1][(sn & 1) * 2]);
        }
        if (kb + 1 < NKT) {
            int nxt = cur ^ 1;
            #pragma unroll
            for (int i = 0; i < 4; i++) {
                int row = sr + i * 32;
                uint4 u;
                u.x = f2tf(av[i].x); u.y = f2tf(av[i].y); u.z = f2tf(av[i].z); u.w = f2tf(av[i].w);
                *(uint4*)&As[nxt][row][kq] = u;
                u.x = f2tf(bv[i].x); u.y = f2tf(bv[i].y); u.z = f2tf(bv[i].z); u.w = f2tf(bv[i].w);
                *(uint4*)&Bs[nxt][row][kq] = u;
            }
        }
        __syncthreads();
    }

    const float* b2e = b2 + e * HH;
    #pragma unroll
    for (int sm = 0; sm < 4; sm++) {
        int rbase = wm * 64 + sm * 16 + grp;
        #pragma unroll
        for (int half = 0; half < 2; half++) {
            int row = rbase + half * 8;
            int slot = slots[row];
            if (slot < 0) continue;
            float rw = g_slot_w[slot];
            float* yrow = g_y + (size_t)slot * HH;
            #pragma unroll
            for (int sn = 0; sn < 8; sn++) {
                int n = ntB + wn * 64 + sn * 8 + 2 * tig;
                #pragma unroll
                for (int cc = 0; cc < 2; cc++) {
                    float y = (acc[sm][sn][half * 2 + cc] + b2e[n + cc]) * rw;
                    yrow[n + cc] = y;
                }
            }
        }
    }
}

// ---------------- kernel 5: out = x + sum_k y[t*4+k] --------------------------
__global__ void finalize_kernel(const float* __restrict__ x,
                                float* __restrict__ out) {
    int idx = blockIdx.x * 256 + threadIdx.x;
    int t = idx >> 10;
    int h = idx & 1023;
    float v = x[idx];
    size_t base = (size_t)t * KTOP * HH + h;
    v += g_y[base];
    v += g_y[base + HH];
    v += g_y[base + 2 * HH];
    v += g_y[base + 3 * HH];
    out[idx] = v;
}

// ---------------- launcher -----------------------------------------------------
extern "C" void kernel_launch(void* const* d_in, const int* in_sizes, int n_in,
                              void* d_out, int out_size) {
    const float* x      = (const float*)d_in[0];
    const float* scale  = (const float*)d_in[1];
    const float* gate_w = (const float*)d_in[2];
    const float* gate_b = (const float*)d_in[3];
    const float* w1     = (const float*)d_in[4];
    const float* b1     = (const float*)d_in[5];
    const float* w2     = (const float*)d_in[6];
    const float* b2     = (const float*)d_in[7];
    float* out = (float*)d_out;

    zero_cnt_kernel<<<1, 32>>>();
    rmsnorm_kernel<<<TT, 256>>>(x, scale);
    gate_kernel<<<TT, 256>>>(gate_w, gate_b);

    dim3 g1(II / BN, TT / BM, NE);
    mlp1_kernel<<<g1, 128>>>(w1, b1);

    dim3 g2(HH / BN, TT / BM, NE);
    mlp2_kernel<<<g2, 128>>>(w2, b2);

    finalize_kernel<<<(TT * HH) / 256, 256>>>(x, out);
}

// round 5
// speedup vs baseline: 3.1876x; 1.0006x over previous
#include <cuda_runtime.h>
#include <math.h>

#define TT 2048
#define HH 1024
#define II 1024
#define NE 16
#define KTOP 4
#define EPSF 1e-5f
#define ALPHAF 1.702f
#define LIMITF 7.0f

#define BM 128
#define BN 128
#define BK 16
#define PAD 20                       // 16+4 words/row -> conflict-free LDSM
#define NSTG 3
#define STG_WORDS (128 * PAD)        // words per stage per operand
#define SMEM_BYTES (NSTG * STG_WORDS * 4 * 2)

// ---------------- scratch (static device globals; no allocation) -------------
__device__ __align__(16) float g_t[TT * HH];            // tf32-rounded rmsnorm out
__device__ __align__(16) float g_s[TT * KTOP * II];     // tf32-rounded swiglu out
__device__ __align__(16) float g_y[TT * KTOP * HH];
__device__ float g_slot_w[TT * KTOP];
__device__ int   g_expert_cnt[NE];
__device__ int   g_expert_slots[NE * TT];

// ---------------- helpers ------------------------------------------------------
__device__ __forceinline__ unsigned f2tf(float f) {
    unsigned r;
    asm("cvt.rna.tf32.f32 %0, %1;" : "=r"(r) : "f"(f));
    return r;
}

__device__ __forceinline__ void mma_tf32(float* d, const unsigned* a, const unsigned* b) {
    asm volatile(
        "mma.sync.aligned.m16n8k8.row.col.f32.tf32.tf32.f32 "
        "{%0,%1,%2,%3}, {%4,%5,%6,%7}, {%8,%9}, {%0,%1,%2,%3};"
        : "+f"(d[0]), "+f"(d[1]), "+f"(d[2]), "+f"(d[3])
        : "r"(a[0]), "r"(a[1]), "r"(a[2]), "r"(a[3]), "r"(b[0]), "r"(b[1]));
}

__device__ __forceinline__ void ldsm4(unsigned* r, unsigned addr) {
    asm volatile("ldmatrix.sync.aligned.m8n8.x4.shared.b16 {%0,%1,%2,%3}, [%4];"
        : "=r"(r[0]), "=r"(r[1]), "=r"(r[2]), "=r"(r[3]) : "r"(addr));
}

__device__ __forceinline__ void cp16(unsigned dst, const void* src) {
    asm volatile("cp.async.cg.shared.global [%0], [%1], 16;" :: "r"(dst), "l"(src));
}
#define CP_COMMIT() asm volatile("cp.async.commit_group;")
#define CP_WAIT1()  asm volatile("cp.async.wait_group 1;")

// ---------------- kernel 0 -----------------------------------------------------
__global__ void zero_cnt_kernel() {
    if (threadIdx.x < NE) g_expert_cnt[threadIdx.x] = 0;
}

// ---------------- kernel 1: fused RMSNorm + gate + top4 + routing -------------
// 256 threads, one token per block. Gate logits computed from UNROUNDED t;
// g_t written tf32-RNA rounded for direct cp.async staging in mlp1.
__global__ void norm_gate_kernel(const float* __restrict__ x,
                                 const float* __restrict__ scale,
                                 const float* __restrict__ gate_w,
                                 const float* __restrict__ gate_b) {
    int t = blockIdx.x;
    int tid = threadIdx.x;
    __shared__ float ts[HH];
    __shared__ float gv[NE];
    __shared__ float red[8];

    float4 v = *((const float4*)(x + (size_t)t * HH) + tid);
    float ss = v.x * v.x + v.y * v.y + v.z * v.z + v.w * v.w;
    #pragma unroll
    for (int o = 16; o; o >>= 1) ss += __shfl_xor_sync(0xffffffffu, ss, o);
    if ((tid & 31) == 0) red[tid >> 5] = ss;
    __syncthreads();
    if (tid < 8) {
        float s2 = red[tid];
        #pragma unroll
        for (int o = 4; o; o >>= 1) s2 += __shfl_xor_sync(0xffu, s2, o);
        if (tid == 0) red[0] = s2;
    }
    __syncthreads();
    float rms = rsqrtf(red[0] * (1.0f / HH) + EPSF);
    float4 sc = *((const float4*)scale + tid);
    float4 tv;
    tv.x = v.x * rms * sc.x; tv.y = v.y * rms * sc.y;
    tv.z = v.z * rms * sc.z; tv.w = v.w * rms * sc.w;
    *((float4*)ts + tid) = tv;
    // rounded copy for the GEMM
    uint4 u;
    u.x = f2tf(tv.x); u.y = f2tf(tv.y); u.z = f2tf(tv.z); u.w = f2tf(tv.w);
    *((uint4*)(g_t + (size_t)t * HH) + tid) = u;
    __syncthreads();

    int g = tid >> 4;
    int j = tid & 15;
    const float* wr = gate_w + g * HH;
    float sum = 0.f;
    for (int h = j; h < HH; h += 16) sum += ts[h] * wr[h];
    #pragma unroll
    for (int o = 8; o; o >>= 1) sum += __shfl_xor_sync(0xffffffffu, sum, o);
    if (j == 0) gv[g] = sum + gate_b[g];
    __syncthreads();

    if (tid == 0) {
        float vals[KTOP];
        int   idx[KTOP];
        bool  used[NE];
        #pragma unroll
        for (int e = 0; e < NE; e++) used[e] = false;
        #pragma unroll
        for (int k = 0; k < KTOP; k++) {
            float best = -INFINITY; int bi = 0;
            for (int e = 0; e < NE; e++)
                if (!used[e] && gv[e] > best) { best = gv[e]; bi = e; }
            used[bi] = true; vals[k] = best; idx[k] = bi;
        }
        float m = vals[0];
        float se = 0.f, w[KTOP];
        #pragma unroll
        for (int k = 0; k < KTOP; k++) { w[k] = __expf(vals[k] - m); se += w[k]; }
        float inv = 1.0f / se;
        #pragma unroll
        for (int k = 0; k < KTOP; k++) {
            int slot = t * KTOP + k;
            g_slot_w[slot] = w[k] * inv;
            int pos = atomicAdd(&g_expert_cnt[idx[k]], 1);
            g_expert_slots[idx[k] * TT + pos] = slot;
        }
    }
}

// ================= tf32 GEMMs ====================================================
// 128x128 block, 4 warps (64x64 warp tile), ldmatrix frags.
// A staged by 3-stage cp.async (source pre-rounded); B staged LDG->cvt->STS with
// one-iteration lookahead.

// ---------------- kernel 3: GEMM1 (even w1 rows) + bias + swiglu --------------
__global__ void __launch_bounds__(128, 2) mlp1_kernel(const float* __restrict__ w1,
                                                      const float* __restrict__ b1) {
    int e = blockIdx.z;
    int cnt = g_expert_cnt[e];
    int mt = blockIdx.y;
    if (mt * BM >= cnt) return;
    int ntB = blockIdx.x * BN;

    extern __shared__ __align__(16) unsigned smem[];
    unsigned* As = smem;                       // [NSTG][128][PAD]
    unsigned* Bs = smem + NSTG * STG_WORDS;    // [NSTG][128][PAD]
    __shared__ int slots[BM];

    int tid = threadIdx.x;
    {
        int idx = mt * BM + tid;
        slots[tid] = (idx < cnt) ? g_expert_slots[e * TT + idx] : -1;
    }
    __syncthreads();

    int lane = tid & 31, wid = tid >> 5;
    int wm = wid & 1, wn = wid >> 1;
    int grp = lane >> 2, tig = lane & 3;
    int rA = (lane & 7) + (((lane >> 3) & 1) << 3);
    int kA = (lane >> 4) << 2;
    int rB = (lane & 7) + ((lane >> 4) << 3);
    int kB = ((lane >> 3) & 1) << 2;
    unsigned aAddr = (unsigned)__cvta_generic_to_shared(&As[(wm * 64 + rA) * PAD + kA]);
    unsigned bAddr = (unsigned)__cvta_generic_to_shared(&Bs[(wn * 64 + rB) * PAD + kB]);

    int sr = tid >> 2;
    int kq = (tid & 3) * 4;
    const float* w1e = w1 + (size_t)e * (2 * II) * HH;
    const float* aptr[4];
    const float* bptr[4];
    unsigned aDst[4];
    #pragma unroll
    for (int i = 0; i < 4; i++) {
        int row = sr + i * 32;
        int s = slots[row];
        aptr[i] = g_t + (size_t)((s >= 0) ? (s >> 2) : 0) * HH + kq;
        bptr[i] = w1e + (size_t)(2 * (ntB + row)) * HH + kq;
        aDst[i] = (unsigned)__cvta_generic_to_shared(&As[row * PAD + kq]);
    }

    float acc[4][8][4] = {};
    float4 bv[4];

    // prologue: B stage0 LDG+cvt+STS; A stage0/1 cp.async; B stage1 LDG
    #pragma unroll
    for (int i = 0; i < 4; i++) {
        float4 b0 = *(const float4*)(bptr[i]);
        uint4 u;
        u.x = f2tf(b0.x); u.y = f2tf(b0.y); u.z = f2tf(b0.z); u.w = f2tf(b0.w);
        *(uint4*)&Bs[(sr + i * 32) * PAD + kq] = u;
    }
    #pragma unroll
    for (int i = 0; i < 4; i++) cp16(aDst[i], aptr[i]);
    CP_COMMIT();
    #pragma unroll
    for (int i = 0; i < 4; i++) cp16(aDst[i] + STG_WORDS * 4, aptr[i] + BK);
    CP_COMMIT();
    #pragma unroll
    for (int i = 0; i < 4; i++) bv[i] = *(const float4*)(bptr[i] + BK);

    const int NKT = HH / BK;
    for (int kb = 0; kb < NKT; kb++) {
        int cur = kb % NSTG;
        CP_WAIT1();
        __syncthreads();
        if (kb + 1 < NKT) {                      // STS B stage kb+1
            int st = (kb + 1) % NSTG;
            #pragma unroll
            for (int i = 0; i < 4; i++) {
                uint4 u;
                u.x = f2tf(bv[i].x); u.y = f2tf(bv[i].y);
                u.z = f2tf(bv[i].z); u.w = f2tf(bv[i].w);
                *(uint4*)&Bs[st * STG_WORDS + (sr + i * 32) * PAD + kq] = u;
            }
        }
        if (kb + 2 < NKT) {                      // A cp.async stage kb+2
            int st = (kb + 2) % NSTG;
            int ko = (kb + 2) * BK;
            #pragma unroll
            for (int i = 0; i < 4; i++)
                cp16(aDst[i] + (unsigned)(st * STG_WORDS * 4), aptr[i] + ko);
        }
        CP_COMMIT();
        if (kb + 2 < NKT) {                      // B LDG stage kb+2
            int ko = (kb + 2) * BK;
            #pragma unroll
            for (int i = 0; i < 4; i++) bv[i] = *(const float4*)(bptr[i] + ko);
        }
        unsigned aOff = aAddr + (unsigned)(cur * STG_WORDS * 4);
        unsigned bOff = bAddr + (unsigned)(cur * STG_WORDS * 4);
        #pragma unroll
        for (int ks = 0; ks < 2; ks++) {
            unsigned afr[4][4], bfr[4][4];
            #pragma unroll
            for (int sm = 0; sm < 4; sm++)
                ldsm4(afr[sm], aOff + (unsigned)((sm * 16 * PAD + ks * 8) * 4));
            #pragma unroll
            for (int p = 0; p < 4; p++)
                ldsm4(bfr[p], bOff + (unsigned)((p * 16 * PAD + ks * 8) * 4));
            #pragma unroll
            for (int sm = 0; sm < 4; sm++)
                #pragma unroll
                for (int sn = 0; sn < 8; sn++)
                    mma_tf32(acc[sm][sn], afr[sm], &bfr[sn >> 1][(sn & 1) * 2]);
        }
    }

    const float* b1e = b1 + e * (2 * II);
    #pragma unroll
    for (int sm = 0; sm < 4; sm++) {
        int rbase = wm * 64 + sm * 16 + grp;
        #pragma unroll
        for (int half = 0; half < 2; half++) {
            int row = rbase + half * 8;
            int slot = slots[row];
            if (slot < 0) continue;
            float* srow = g_s + (size_t)slot * II;
            #pragma unroll
            for (int sn = 0; sn < 8; sn++) {
                int n = ntB + wn * 64 + sn * 8 + 2 * tig;
                #pragma unroll
                for (int cc = 0; cc < 2; cc++) {
                    float hsum = acc[sm][sn][half * 2 + cc] + b1e[2 * (n + cc)];
                    float gl = fminf(hsum, LIMITF);
                    float sig = 1.0f / (1.0f + __expf(-ALPHAF * gl));
                    // store tf32-rounded so mlp2 can cp.async it directly
                    srow[n + cc] = __uint_as_float(f2tf(gl * sig * (LIMITF + 1.0f)));
                }
            }
        }
    }
}

// ---------------- kernel 4: GEMM2 + bias, scaled by routing weight ------------
__global__ void __launch_bounds__(128, 2) mlp2_kernel(const float* __restrict__ w2,
                                                      const float* __restrict__ b2) {
    int e = blockIdx.z;
    int cnt = g_expert_cnt[e];
    int mt = blockIdx.y;
    if (mt * BM >= cnt) return;
    int ntB = blockIdx.x * BN;

    extern __shared__ __align__(16) unsigned smem[];
    unsigned* As = smem;
    unsigned* Bs = smem + NSTG * STG_WORDS;
    __shared__ int slots[BM];

    int tid = threadIdx.x;
    {
        int idx = mt * BM + tid;
        slots[tid] = (idx < cnt) ? g_expert_slots[e * TT + idx] : -1;
    }
    __syncthreads();

    int lane = tid & 31, wid = tid >> 5;
    int wm = wid & 1, wn = wid >> 1;
    int grp = lane >> 2, tig = lane & 3;
    int rA = (lane & 7) + (((lane >> 3) & 1) << 3);
    int kA = (lane >> 4) << 2;
    int rB = (lane & 7) + ((lane >> 4) << 3);
    int kB = ((lane >> 3) & 1) << 2;
    unsigned aAddr = (unsigned)__cvta_generic_to_shared(&As[(wm * 64 + rA) * PAD + kA]);
    unsigned bAddr = (unsigned)__cvta_generic_to_shared(&Bs[(wn * 64 + rB) * PAD + kB]);

    int sr = tid >> 2;
    int kq = (tid & 3) * 4;
    const float* w2e = w2 + (size_t)e * HH * II;
    const float* aptr[4];
    const float* bptr[4];
    unsigned aDst[4];
    #pragma unroll
    for (int i = 0; i < 4; i++) {
        int row = sr + i * 32;
        int s = slots[row];
        aptr[i] = g_s + (size_t)((s >= 0) ? s : 0) * II + kq;
        bptr[i] = w2e + (size_t)(ntB + row) * II + kq;
        aDst[i] = (unsigned)__cvta_generic_to_shared(&As[row * PAD + kq]);
    }

    float acc[4][8][4] = {};
    float4 bv[4];

    #pragma unroll
    for (int i = 0; i < 4; i++) {
        float4 b0 = *(const float4*)(bptr[i]);
        uint4 u;
        u.x = f2tf(b0.x); u.y = f2tf(b0.y); u.z = f2tf(b0.z); u.w = f2tf(b0.w);
        *(uint4*)&Bs[(sr + i * 32) * PAD + kq] = u;
    }
    #pragma unroll
    for (int i = 0; i < 4; i++) cp16(aDst[i], aptr[i]);
    CP_COMMIT();
    #pragma unroll
    for (int i = 0; i < 4; i++) cp16(aDst[i] + STG_WORDS * 4, aptr[i] + BK);
    CP_COMMIT();
    #pragma unroll
    for (int i = 0; i < 4; i++) bv[i] = *(const float4*)(bptr[i] + BK);

    const int NKT = II / BK;
    for (int kb = 0; kb < NKT; kb++) {
        int cur = kb % NSTG;
        CP_WAIT1();
        __syncthreads();
        if (kb + 1 < NKT) {
            int st = (kb + 1) % NSTG;
            #pragma unroll
            for (int i = 0; i < 4; i++) {
                uint4 u;
                u.x = f2tf(bv[i].x); u.y = f2tf(bv[i].y);
                u.z = f2tf(bv[i].z); u.w = f2tf(bv[i].w);
                *(uint4*)&Bs[st * STG_WORDS + (sr + i * 32) * PAD + kq] = u;
            }
        }
        if (kb + 2 < NKT) {
            int st = (kb + 2) % NSTG;
            int ko = (kb + 2) * BK;
            #pragma unroll
            for (int i = 0; i < 4; i++)
                cp16(aDst[i] + (unsigned)(st * STG_WORDS * 4), aptr[i] + ko);
        }
        CP_COMMIT();
        if (kb + 2 < NKT) {
            int ko = (kb + 2) * BK;
            #pragma unroll
            for (int i = 0; i < 4; i++) bv[i] = *(const float4*)(bptr[i] + ko);
        }
        unsigned aOff = aAddr + (unsigned)(cur * STG_WORDS * 4);
        unsigned bOff = bAddr + (unsigned)(cur * STG_WORDS * 4);
        #pragma unroll
        for (int ks = 0; ks < 2; ks++) {
            unsigned afr[4][4], bfr[4][4];
            #pragma unroll
            for (int sm = 0; sm < 4; sm++)
                ldsm4(afr[sm], aOff + (unsigned)((sm * 16 * PAD + ks * 8) * 4));
            #pragma unroll
            for (int p = 0; p < 4; p++)
                ldsm4(bfr[p], bOff + (unsigned)((p * 16 * PAD + ks * 8) * 4));
            #pragma unroll
            for (int sm = 0; sm < 4; sm++)
                #pragma unroll
                for (int sn = 0; sn < 8; sn++)
                    mma_tf32(acc[sm][sn], afr[sm], &bfr[sn >> 1][(sn & 1) * 2]);
        }
    }

    const float* b2e = b2 + e * HH;
    #pragma unroll
    for (int sm = 0; sm < 4; sm++) {
        int rbase = wm * 64 + sm * 16 + grp;
        #pragma unroll
        for (int half = 0; half < 2; half++) {
            int row = rbase + half * 8;
            int slot = slots[row];
            if (slot < 0) continue;
            float rw = g_slot_w[slot];
            float* yrow = g_y + (size_t)slot * HH;
            #pragma unroll
            for (int sn = 0; sn < 8; sn++) {
                int n = ntB + wn * 64 + sn * 8 + 2 * tig;
                #pragma unroll
                for (int cc = 0; cc < 2; cc++)
                    yrow[n + cc] = (acc[sm][sn][half * 2 + cc] + b2e[n + cc]) * rw;
            }
        }
    }
}

// ---------------- kernel 5: out = x + sum_k y[t*4+k]  (vectorized) ------------
__global__ void finalize_kernel(const float* __restrict__ x,
                                float* __restrict__ out) {
    int q = blockIdx.x * 256 + threadIdx.x;          // float4 index
    int t = q >> 8;                                   // 256 float4 per token
    int h4 = q & 255;
    float4 v = *((const float4*)x + q);
    const float4* yb = (const float4*)(g_y + (size_t)t * KTOP * HH) + h4;
    float4 a = yb[0], b = yb[256], c = yb[512], d = yb[768];
    v.x += a.x + b.x + c.x + d.x;
    v.y += a.y + b.y + c.y + d.y;
    v.z += a.z + b.z + c.z + d.z;
    v.w += a.w + b.w + c.w + d.w;
    *((float4*)out + q) = v;
}

// ---------------- launcher -----------------------------------------------------
extern "C" void kernel_launch(void* const* d_in, const int* in_sizes, int n_in,
                              void* d_out, int out_size) {
    const float* x      = (const float*)d_in[0];
    const float* scale  = (const float*)d_in[1];
    const float* gate_w = (const float*)d_in[2];
    const float* gate_b = (const float*)d_in[3];
    const float* w1     = (const float*)d_in[4];
    const float* b1     = (const float*)d_in[5];
    const float* w2     = (const float*)d_in[6];
    const float* b2     = (const float*)d_in[7];
    float* out = (float*)d_out;

    cudaFuncSetAttribute(mlp1_kernel, cudaFuncAttributeMaxDynamicSharedMemorySize, SMEM_BYTES);
    cudaFuncSetAttribute(mlp2_kernel, cudaFuncAttributeMaxDynamicSharedMemorySize, SMEM_BYTES);

    zero_cnt_kernel<<<1, 32>>>();
    norm_gate_kernel<<<TT, 256>>>(x, scale, gate_w, gate_b);

    dim3 g1(II / BN, TT / BM, NE);
    mlp1_kernel<<<g1, 128, SMEM_BYTES>>>(w1, b1);

    dim3 g2(HH / BN, TT / BM, NE);
    mlp2_kernel<<<g2, 128, SMEM_BYTES>>>(w2, b2);

    finalize_kernel<<<(TT * HH) / 1024, 256>>>(x, out);
}